// round 14
// baseline (speedup 1.0000x reference)
#include <cuda_runtime.h>
#include <cuda_fp16.h>
#include <cstdint>

#define NB 2048   // batch
#define PP 196    // patches
#define DD 768    // patch dim
#define OO 512    // output dim
#define KT 16     // top-k
#define MTOT (NB * KT)   // 32768 gathered rows

// ---------------- device scratch (no allocations allowed) -------------------
__device__ int    g_topk[MTOT];
__device__ __half g_A[MTOT * DD];        // gathered patches, fp16
__device__ __half g_F[NB * 2 * OO];      // fusion input [cls | local], fp16
__device__ __half g_WpH[OO * DD];
__device__ __half g_WfH[OO * 2 * OO];
__device__ float  g_P[2 * NB * OO];      // split-K partials for fusion GEMM

// ---------------- helpers ----------------------------------------------------
__device__ __forceinline__ uint32_t smem_u32(const void* p) {
    uint32_t a;
    asm("{ .reg .u64 t; cvta.to.shared.u64 t, %1; cvt.u32.u64 %0, t; }" : "=r"(a) : "l"(p));
    return a;
}
#define CP_ASYNC16(dst, src) \
    asm volatile("cp.async.cg.shared.global [%0], [%1], 16;" :: "r"(dst), "l"(src) : "memory")
#define CP_COMMIT() asm volatile("cp.async.commit_group;" ::: "memory")
#define CP_WAIT2()  asm volatile("cp.async.wait_group 2;" ::: "memory")
#define LDMATRIX_X4(r, addr) \
    asm volatile("ldmatrix.sync.aligned.m8n8.x4.shared.b16 {%0,%1,%2,%3}, [%4];" \
        : "=r"((r)[0]), "=r"((r)[1]), "=r"((r)[2]), "=r"((r)[3]) : "r"(addr))
#define MMA16816(d, a, b0, b1) \
    asm volatile("mma.sync.aligned.m16n8k16.row.col.f32.f16.f16.f32 " \
        "{%0,%1,%2,%3}, {%4,%5,%6,%7}, {%8,%9}, {%0,%1,%2,%3};" \
        : "+f"((d)[0]), "+f"((d)[1]), "+f"((d)[2]), "+f"((d)[3]) \
        : "r"((a)[0]), "r"((a)[1]), "r"((a)[2]), "r"((a)[3]), "r"(b0), "r"(b1))

__device__ __forceinline__ uint2 f4_to_h4(float4 v) {
    __half2 h0 = __floats2half2_rn(v.x, v.y);
    __half2 h1 = __floats2half2_rn(v.z, v.w);
    return make_uint2(*(uint32_t*)&h0, *(uint32_t*)&h1);
}

// ---------------------------------------------------------------------------
// Kernel 1 (512 threads): blocks [0, NB): per-patch squared L2 norms
// (16 warps x 4-row streams -> high MLP) + single-warp register top-16 +
// gather (16 warps x 1 slot) into fp16 g_A.
// Blocks [NB, NB+PREP_BLOCKS): weight fp32->fp16 + cls half of g_F.
// ---------------------------------------------------------------------------
#define PQ 49                       // 196 / 4
#define NWP4 (OO * DD / 4)          // 98304 float4
#define NWF4 (OO * 2 * OO / 4)      // 131072 float4
#define NCLS4 (NB * OO / 4)         // 262144 float4
#define PREP_BLOCKS ((NWP4 + NWF4 + NCLS4) / 512)   // 960

__global__ void __launch_bounds__(512) norm_topk_kernel(
    const float* __restrict__ pt, const float* __restrict__ Wp,
    const float* __restrict__ Wf, const float* __restrict__ cls) {
    if (blockIdx.x >= NB) {
        // ---- prep section (vectorized float4 -> half2x2)
        int i = (blockIdx.x - NB) * 512 + threadIdx.x;
        if (i < NWP4) {
            ((uint2*)g_WpH)[i] = f4_to_h4(((const float4*)Wp)[i]);
        } else if (i < NWP4 + NWF4) {
            int j = i - NWP4;
            ((uint2*)g_WfH)[j] = f4_to_h4(((const float4*)Wf)[j]);
        } else {
            int j = i - NWP4 - NWF4;
            int n = j >> 7, q = j & 127;        // 128 float4 per cls row
            ((uint2*)(g_F + (size_t)n * 2 * OO))[q] = f4_to_h4(((const float4*)cls)[j]);
        }
        return;
    }

    int n = blockIdx.x;
    __shared__ float norms[PP];
    __shared__ int   sel[KT];

    const float* base = pt + (size_t)n * PP * DD;
    int warp = threadIdx.x >> 5, lane = threadIdx.x & 31;

    // four rows per warp-iteration: p, p+49, p+98, p+147; 16 warps stride 16
    for (int p = warp; p < PQ; p += 16) {
        const float4* r0 = (const float4*)(base + p * DD);
        const float4* r1 = (const float4*)(base + (p + PQ) * DD);
        const float4* r2 = (const float4*)(base + (p + 2 * PQ) * DD);
        const float4* r3 = (const float4*)(base + (p + 3 * PQ) * DD);
        float s0 = 0.f, s1 = 0.f, s2 = 0.f, s3 = 0.f;
        #pragma unroll
        for (int j = 0; j < (DD / 4) / 32; j++) {   // 6 iters x 4 rows
            float4 q0 = r0[j * 32 + lane];
            float4 q1 = r1[j * 32 + lane];
            float4 q2 = r2[j * 32 + lane];
            float4 q3 = r3[j * 32 + lane];
            s0 += q0.x * q0.x + q0.y * q0.y + q0.z * q0.z + q0.w * q0.w;
            s1 += q1.x * q1.x + q1.y * q1.y + q1.z * q1.z + q1.w * q1.w;
            s2 += q2.x * q2.x + q2.y * q2.y + q2.z * q2.z + q2.w * q2.w;
            s3 += q3.x * q3.x + q3.y * q3.y + q3.z * q3.z + q3.w * q3.w;
        }
        #pragma unroll
        for (int o = 16; o; o >>= 1) {
            s0 += __shfl_xor_sync(0xffffffffu, s0, o);
            s1 += __shfl_xor_sync(0xffffffffu, s1, o);
            s2 += __shfl_xor_sync(0xffffffffu, s2, o);
            s3 += __shfl_xor_sync(0xffffffffu, s3, o);
        }
        if (lane == 0) {
            norms[p] = s0;
            norms[p + PQ] = s1;
            norms[p + 2 * PQ] = s2;
            norms[p + 3 * PQ] = s3;
        }
    }
    __syncthreads();

    if (warp == 0) {
        float v[7];
        #pragma unroll
        for (int j = 0; j < 7; j++) {
            int p = lane + 32 * j;
            v[j] = (p < PP) ? norms[p] : -1e30f;
        }
        #pragma unroll 1
        for (int it = 0; it < KT; it++) {
            float mx = v[0]; int mj = 0;
            #pragma unroll
            for (int j = 1; j < 7; j++) if (v[j] > mx) { mx = v[j]; mj = j; }
            float bmx = mx; int bl = lane;
            #pragma unroll
            for (int o = 16; o; o >>= 1) {
                float om = __shfl_xor_sync(0xffffffffu, bmx, o);
                int   ol = __shfl_xor_sync(0xffffffffu, bl, o);
                if (om > bmx || (om == bmx && ol < bl)) { bmx = om; bl = ol; }
            }
            int wmj = __shfl_sync(0xffffffffu, mj, bl);
            if (lane == bl) v[mj] = -1e30f;
            if (lane == 0) {
                int p = bl + 32 * wmj;
                g_topk[n * KT + it] = p;
                sel[it] = p;
            }
        }
    }
    __syncthreads();

    // gather: 16 warps x 1 slot each, rows still L2-resident
    {
        int slot = warp;
        const float4* src = (const float4*)(base + sel[slot] * DD);
        uint2* dst = (uint2*)(g_A + (size_t)(n * KT + slot) * DD);
        #pragma unroll
        for (int j = 0; j < 6; j++)
            dst[j * 32 + lane] = f4_to_h4(src[j * 32 + lane]);
    }
}

// ---------------------------------------------------------------------------
// Kernel 2/3: fp16 HMMA GEMM, tile-size templated. 8 warps (2m x 4n),
// BK=64, cp.async 4-stage single-sync pipeline, 144B padded rows.
//   C[m,o] = sum_k A[m,k] * B[o,k], K window selected by blockIdx.z (split-K).
// MAXEPI: max over 16-row groups -> fp16 into outp[:, 512:];
// else fp32 store to outp + z * NB*OO (split-K partial buffers).
// ---------------------------------------------------------------------------
#define ROWB  144

template<int BM, int BN, int NCH, bool MAXEPI>
__global__ void __launch_bounds__(256, 1) gemm_mma(
    const __half* __restrict__ A, const __half* __restrict__ B,
    int ldk, void* __restrict__ outp)
{
    constexpr int SMA = BM * ROWB;
    constexpr int SMB = BN * ROWB;
    constexpr int STAGE = SMA + SMB;
    constexpr int WTM = BM / 2;          // warp tile m
    constexpr int WTN = BN / 4;          // warp tile n
    constexpr int MF = WTM / 16;         // a-frags
    constexpr int NBB = WTN / 16;        // b ldmatrix blocks
    constexpr int NF = WTN / 8;          // n-frags

    extern __shared__ char smem[];
    uint32_t sb = smem_u32(smem);
    int tid = threadIdx.x, lane = tid & 31, wid = tid >> 5;
    int bn = blockIdx.x, bm = blockIdx.y;
    int koff = blockIdx.z * (NCH * 64);
    int warp_m = wid & 1, warp_n = wid >> 1;

    const __half* Ab = A + koff;
    const __half* Bb = B + koff;

    auto issue = [&](int c, int b) {
        int kt = c * 64;
        uint32_t s0 = sb + b * STAGE;
        #pragma unroll
        for (int i = 0; i < BM * 8 / 256; i++) {
            int idx = i * 256 + tid, r = idx >> 3, q = idx & 7;
            CP_ASYNC16(s0 + r * ROWB + q * 16,
                       (const char*)(Ab + (size_t)(bm * BM + r) * ldk + kt) + q * 16);
        }
        #pragma unroll
        for (int i = 0; i < BN * 8 / 256; i++) {
            int idx = i * 256 + tid, r = idx >> 3, q = idx & 7;
            CP_ASYNC16(s0 + SMA + r * ROWB + q * 16,
                       (const char*)(Bb + (size_t)(bn * BN + r) * ldk + kt) + q * 16);
        }
        CP_COMMIT();
    };

    float acc[MF][NF][4] = {};

    issue(0, 0);
    issue(1, 1);
    issue(2, 2);

    for (int c = 0; c < NCH; c++) {
        CP_WAIT2();
        __syncthreads();   // chunk c visible; buffer (c+3)&3 free
        if (c + 3 < NCH) issue(c + 3, (c + 3) & 3); else CP_COMMIT();

        uint32_t s0 = sb + (c & 3) * STAGE;
        #pragma unroll
        for (int ks = 0; ks < 4; ks++) {
            uint32_t a[MF][4], b[NBB][4];
            uint32_t arow = warp_m * WTM + (lane & 15);
            uint32_t acol = (ks * 16 + (lane >> 4) * 8) * 2;
            #pragma unroll
            for (int mf = 0; mf < MF; mf++)
                LDMATRIX_X4(a[mf], s0 + (arow + mf * 16) * ROWB + acol);
            uint32_t brow = warp_n * WTN + (lane & 7) + ((lane >> 4) & 1) * 8;
            uint32_t bcol = (ks * 16 + ((lane >> 3) & 1) * 8) * 2;
            #pragma unroll
            for (int nb = 0; nb < NBB; nb++)
                LDMATRIX_X4(b[nb], s0 + SMA + (brow + nb * 16) * ROWB + bcol);
            #pragma unroll
            for (int mf = 0; mf < MF; mf++)
                #pragma unroll
                for (int nf = 0; nf < NF; nf++)
                    MMA16816(acc[mf][nf], a[mf], b[nf >> 1][(nf & 1) * 2], b[nf >> 1][(nf & 1) * 2 + 1]);
        }
    }

    if (MAXEPI) {
        __half* fout = (__half*)outp;
        #pragma unroll
        for (int mf = 0; mf < MF; mf++) {
            int nrow = bm * (BM / 16) + warp_m * MF + mf;    // batch index
            #pragma unroll
            for (int nf = 0; nf < NF; nf++) {
                float m0 = fmaxf(acc[mf][nf][0], acc[mf][nf][2]);
                float m1 = fmaxf(acc[mf][nf][1], acc[mf][nf][3]);
                #pragma unroll
                for (int o = 4; o < 32; o <<= 1) {
                    m0 = fmaxf(m0, __shfl_xor_sync(0xffffffffu, m0, o));
                    m1 = fmaxf(m1, __shfl_xor_sync(0xffffffffu, m1, o));
                }
                if (lane < 4) {
                    int col = OO + bn * BN + warp_n * WTN + nf * 8 + lane * 2;
                    __half2 h = __floats2half2_rn(m0, m1);
                    *(__half2*)&fout[(size_t)nrow * (2 * OO) + col] = h;
                }
            }
        }
    } else {
        float* out = (float*)outp + (size_t)blockIdx.z * NB * OO;
        #pragma unroll
        for (int mf = 0; mf < MF; mf++) {
            int r0 = bm * BM + warp_m * WTM + mf * 16 + (lane >> 2);
            #pragma unroll
            for (int nf = 0; nf < NF; nf++) {
                int col = bn * BN + warp_n * WTN + nf * 8 + (lane & 3) * 2;
                *(float2*)&out[(size_t)r0 * OO + col] =
                    make_float2(acc[mf][nf][0], acc[mf][nf][1]);
                *(float2*)&out[(size_t)(r0 + 8) * OO + col] =
                    make_float2(acc[mf][nf][2], acc[mf][nf][3]);
            }
        }
    }
}

// ---------------------------------------------------------------------------
// Kernel 4: sum split-K partials + row L2 normalize -> out
// 2 rows per block (grid NB/2), float4 loads. Warps 0-3 row 0, warps 4-7 row 1.
// ---------------------------------------------------------------------------
__global__ void normalize_kernel(float* __restrict__ out) {
    __shared__ float red[8];
    __shared__ float invs[2];

    int t = threadIdx.x;
    int r = t >> 7;                      // 0 or 1 (local row)
    int c = t & 127;                     // float4 index within row
    int n = blockIdx.x * 2 + r;
    int warp = t >> 5, lane = t & 31;

    float4 a = ((const float4*)(g_P + (size_t)n * OO))[c];
    float4 b = ((const float4*)(g_P + (size_t)(NB + n) * OO))[c];
    float4 v = make_float4(a.x + b.x, a.y + b.y, a.z + b.z, a.w + b.w);
    float s = v.x * v.x + v.y * v.y + v.z * v.z + v.w * v.w;
    #pragma unroll
    for (int o = 16; o; o >>= 1) s += __shfl_xor_sync(0xffffffffu, s, o);
    if (lane == 0) red[warp] = s;
    __syncthreads();
    if (t < 2) {
        float tot = red[t * 4] + red[t * 4 + 1] + red[t * 4 + 2] + red[t * 4 + 3];
        invs[t] = 1.f / fmaxf(sqrtf(tot), 1e-12f);
    }
    __syncthreads();
    float inv = invs[r];
    v.x *= inv; v.y *= inv; v.z *= inv; v.w *= inv;
    ((float4*)(out + (size_t)n * OO))[c] = v;
}

// ---------------------------------------------------------------------------
extern "C" void kernel_launch(void* const* d_in, const int* in_sizes, int n_in,
                              void* d_out, int out_size) {
    const float* cls = (const float*)d_in[0];   // (2048, 512)
    const float* pt  = (const float*)d_in[1];   // (2048, 196, 768)
    const float* Wp  = (const float*)d_in[2];   // (512, 768)
    const float* Wf  = (const float*)d_in[3];   // (512, 1024)
    float* out = (float*)d_out;                 // (2048, 512)

    __half *a_p, *f_p, *wp_p, *wf_p;
    float* p_p;
    cudaGetSymbolAddress((void**)&a_p,  g_A);
    cudaGetSymbolAddress((void**)&f_p,  g_F);
    cudaGetSymbolAddress((void**)&wp_p, g_WpH);
    cudaGetSymbolAddress((void**)&wf_p, g_WfH);
    cudaGetSymbolAddress((void**)&p_p,  g_P);

    // local GEMM: BM=64, BN=256 -> grid (2, 512) = 1024 CTAs (98.8% wave eff)
    constexpr int SM_LOCAL = 4 * (64 + 256) * ROWB;    // 184320
    // fuse GEMM: BM=64, BN=128, split-K=2 -> grid (4, 32, 2) = 256 CTAs
    constexpr int SM_FUSE  = 4 * (64 + 128) * ROWB;    // 110592

    cudaFuncSetAttribute(gemm_mma<64, 256, DD / 64, true>,
                         cudaFuncAttributeMaxDynamicSharedMemorySize, SM_LOCAL);
    cudaFuncSetAttribute(gemm_mma<64, 128, (2 * OO) / 128, false>,
                         cudaFuncAttributeMaxDynamicSharedMemorySize, SM_FUSE);

    norm_topk_kernel<<<NB + PREP_BLOCKS, 512>>>(pt, Wp, Wf, cls);
    gemm_mma<64, 256, DD / 64, true><<<dim3(OO / 256, MTOT / 64), 256, SM_LOCAL>>>(
        a_p, wp_p, DD, f_p);
    gemm_mma<64, 128, (2 * OO) / 128, false>
        <<<dim3(OO / 128, NB / 64, 2), 256, SM_FUSE>>>(f_p, wf_p, 2 * OO, p_p);
    normalize_kernel<<<NB / 2, 256>>>(out);
}

// round 15
// speedup vs baseline: 1.0391x; 1.0391x over previous
#include <cuda_runtime.h>
#include <cuda_fp16.h>
#include <cstdint>

#define NB 2048   // batch
#define PP 196    // patches
#define DD 768    // patch dim
#define OO 512    // output dim
#define KT 16     // top-k
#define MTOT (NB * KT)   // 32768 gathered rows

// ---------------- device scratch (no allocations allowed) -------------------
__device__ __half g_A[MTOT * DD];        // gathered patches, fp16
__device__ __half g_F[NB * 2 * OO];      // fusion input [cls | local], fp16
__device__ __half g_WpH[OO * DD];
__device__ __half g_WfH[OO * 2 * OO];
__device__ float  g_P[2 * NB * OO];      // split-K partials for fusion GEMM

// ---------------- helpers ----------------------------------------------------
__device__ __forceinline__ uint32_t smem_u32(const void* p) {
    uint32_t a;
    asm("{ .reg .u64 t; cvta.to.shared.u64 t, %1; cvt.u32.u64 %0, t; }" : "=r"(a) : "l"(p));
    return a;
}
#define CP_ASYNC16(dst, src) \
    asm volatile("cp.async.cg.shared.global [%0], [%1], 16;" :: "r"(dst), "l"(src) : "memory")
#define CP_COMMIT() asm volatile("cp.async.commit_group;" ::: "memory")
#define CP_WAIT2()  asm volatile("cp.async.wait_group 2;" ::: "memory")
#define LDMATRIX_X4(r, addr) \
    asm volatile("ldmatrix.sync.aligned.m8n8.x4.shared.b16 {%0,%1,%2,%3}, [%4];" \
        : "=r"((r)[0]), "=r"((r)[1]), "=r"((r)[2]), "=r"((r)[3]) : "r"(addr))
#define MMA16816(d, a, b0, b1) \
    asm volatile("mma.sync.aligned.m16n8k16.row.col.f32.f16.f16.f32 " \
        "{%0,%1,%2,%3}, {%4,%5,%6,%7}, {%8,%9}, {%0,%1,%2,%3};" \
        : "+f"((d)[0]), "+f"((d)[1]), "+f"((d)[2]), "+f"((d)[3]) \
        : "r"((a)[0]), "r"((a)[1]), "r"((a)[2]), "r"((a)[3]), "r"(b0), "r"(b1))

__device__ __forceinline__ uint2 f4_to_h4(float4 v) {
    __half2 h0 = __floats2half2_rn(v.x, v.y);
    __half2 h1 = __floats2half2_rn(v.z, v.w);
    return make_uint2(*(uint32_t*)&h0, *(uint32_t*)&h1);
}

// ---------------------------------------------------------------------------
// Kernel 1 (512 threads): blocks [0, NB): per-patch squared L2 norms
// (16 warps x 4-row streams -> high MLP) + single-warp register top-16 +
// gather (16 warps x 1 slot) into fp16 g_A.
// Blocks [NB, NB+PREP_BLOCKS): weight fp32->fp16 + cls half of g_F.
// ---------------------------------------------------------------------------
#define PQ 49                       // 196 / 4
#define NWP4 (OO * DD / 4)          // 98304 float4
#define NWF4 (OO * 2 * OO / 4)      // 131072 float4
#define NCLS4 (NB * OO / 4)         // 262144 float4
#define PREP_BLOCKS ((NWP4 + NWF4 + NCLS4) / 512)   // 960

__global__ void __launch_bounds__(512) norm_topk_kernel(
    const float* __restrict__ pt, const float* __restrict__ Wp,
    const float* __restrict__ Wf, const float* __restrict__ cls) {
    if (blockIdx.x >= NB) {
        // ---- prep section (vectorized float4 -> half2x2)
        int i = (blockIdx.x - NB) * 512 + threadIdx.x;
        if (i < NWP4) {
            ((uint2*)g_WpH)[i] = f4_to_h4(((const float4*)Wp)[i]);
        } else if (i < NWP4 + NWF4) {
            int j = i - NWP4;
            ((uint2*)g_WfH)[j] = f4_to_h4(((const float4*)Wf)[j]);
        } else {
            int j = i - NWP4 - NWF4;
            int n = j >> 7, q = j & 127;        // 128 float4 per cls row
            ((uint2*)(g_F + (size_t)n * 2 * OO))[q] = f4_to_h4(((const float4*)cls)[j]);
        }
        return;
    }

    int n = blockIdx.x;
    __shared__ float norms[PP];
    __shared__ int   sel[KT];

    const float* base = pt + (size_t)n * PP * DD;
    int warp = threadIdx.x >> 5, lane = threadIdx.x & 31;

    // four rows per warp-iteration: p, p+49, p+98, p+147; 16 warps stride 16
    for (int p = warp; p < PQ; p += 16) {
        const float4* r0 = (const float4*)(base + p * DD);
        const float4* r1 = (const float4*)(base + (p + PQ) * DD);
        const float4* r2 = (const float4*)(base + (p + 2 * PQ) * DD);
        const float4* r3 = (const float4*)(base + (p + 3 * PQ) * DD);
        float s0 = 0.f, s1 = 0.f, s2 = 0.f, s3 = 0.f;
        #pragma unroll
        for (int j = 0; j < (DD / 4) / 32; j++) {   // 6 iters x 4 rows
            float4 q0 = r0[j * 32 + lane];
            float4 q1 = r1[j * 32 + lane];
            float4 q2 = r2[j * 32 + lane];
            float4 q3 = r3[j * 32 + lane];
            s0 += q0.x * q0.x + q0.y * q0.y + q0.z * q0.z + q0.w * q0.w;
            s1 += q1.x * q1.x + q1.y * q1.y + q1.z * q1.z + q1.w * q1.w;
            s2 += q2.x * q2.x + q2.y * q2.y + q2.z * q2.z + q2.w * q2.w;
            s3 += q3.x * q3.x + q3.y * q3.y + q3.z * q3.z + q3.w * q3.w;
        }
        #pragma unroll
        for (int o = 16; o; o >>= 1) {
            s0 += __shfl_xor_sync(0xffffffffu, s0, o);
            s1 += __shfl_xor_sync(0xffffffffu, s1, o);
            s2 += __shfl_xor_sync(0xffffffffu, s2, o);
            s3 += __shfl_xor_sync(0xffffffffu, s3, o);
        }
        if (lane == 0) {
            norms[p] = s0;
            norms[p + PQ] = s1;
            norms[p + 2 * PQ] = s2;
            norms[p + 3 * PQ] = s3;
        }
    }
    __syncthreads();

    if (warp == 0) {
        float v[7];
        #pragma unroll
        for (int j = 0; j < 7; j++) {
            int p = lane + 32 * j;
            v[j] = (p < PP) ? norms[p] : -1e30f;
        }
        #pragma unroll 1
        for (int it = 0; it < KT; it++) {
            float mx = v[0]; int mj = 0;
            #pragma unroll
            for (int j = 1; j < 7; j++) if (v[j] > mx) { mx = v[j]; mj = j; }
            float bmx = mx; int bl = lane;
            #pragma unroll
            for (int o = 16; o; o >>= 1) {
                float om = __shfl_xor_sync(0xffffffffu, bmx, o);
                int   ol = __shfl_xor_sync(0xffffffffu, bl, o);
                if (om > bmx || (om == bmx && ol < bl)) { bmx = om; bl = ol; }
            }
            int wmj = __shfl_sync(0xffffffffu, mj, bl);
            if (lane == bl) v[mj] = -1e30f;
            if (lane == 0) sel[it] = bl + 32 * wmj;
        }
    }
    __syncthreads();

    // gather: 16 warps x 1 slot each, rows still L2-resident
    {
        int slot = warp;
        const float4* src = (const float4*)(base + sel[slot] * DD);
        uint2* dst = (uint2*)(g_A + (size_t)(n * KT + slot) * DD);
        #pragma unroll
        for (int j = 0; j < 6; j++)
            dst[j * 32 + lane] = f4_to_h4(src[j * 32 + lane]);
    }
}

// ---------------------------------------------------------------------------
// Kernel 2/3: fp16 HMMA GEMM, tile-size templated. 8 warps (2m x 4n),
// BK=64, cp.async 4-stage single-sync pipeline, 144B padded rows.
//   C[m,o] = sum_k A[m,k] * B[o,k], K window selected by blockIdx.z (split-K).
// MAXEPI: max over 16-row groups -> fp16 into outp[:, 512:];
// else fp32 store to outp + z * NB*OO (split-K partial buffers).
// ---------------------------------------------------------------------------
#define ROWB  144

template<int BM, int BN, int NCH, bool MAXEPI>
__global__ void __launch_bounds__(256, 1) gemm_mma(
    const __half* __restrict__ A, const __half* __restrict__ B,
    int ldk, void* __restrict__ outp)
{
    constexpr int SMA = BM * ROWB;
    constexpr int SMB = BN * ROWB;
    constexpr int STAGE = SMA + SMB;
    constexpr int WTM = BM / 2;          // warp tile m
    constexpr int WTN = BN / 4;          // warp tile n
    constexpr int MF = WTM / 16;         // a-frags
    constexpr int NBB = WTN / 16;        // b ldmatrix blocks
    constexpr int NF = WTN / 8;          // n-frags

    extern __shared__ char smem[];
    uint32_t sb = smem_u32(smem);
    int tid = threadIdx.x, lane = tid & 31, wid = tid >> 5;
    int bn = blockIdx.x, bm = blockIdx.y;
    int koff = blockIdx.z * (NCH * 64);
    int warp_m = wid & 1, warp_n = wid >> 1;

    const __half* Ab = A + koff;
    const __half* Bb = B + koff;

    auto issue = [&](int c, int b) {
        int kt = c * 64;
        uint32_t s0 = sb + b * STAGE;
        #pragma unroll
        for (int i = 0; i < BM * 8 / 256; i++) {
            int idx = i * 256 + tid, r = idx >> 3, q = idx & 7;
            CP_ASYNC16(s0 + r * ROWB + q * 16,
                       (const char*)(Ab + (size_t)(bm * BM + r) * ldk + kt) + q * 16);
        }
        #pragma unroll
        for (int i = 0; i < BN * 8 / 256; i++) {
            int idx = i * 256 + tid, r = idx >> 3, q = idx & 7;
            CP_ASYNC16(s0 + SMA + r * ROWB + q * 16,
                       (const char*)(Bb + (size_t)(bn * BN + r) * ldk + kt) + q * 16);
        }
        CP_COMMIT();
    };

    float acc[MF][NF][4] = {};

    issue(0, 0);
    issue(1, 1);
    issue(2, 2);

    for (int c = 0; c < NCH; c++) {
        CP_WAIT2();
        __syncthreads();   // chunk c visible; buffer (c+3)&3 free
        if (c + 3 < NCH) issue(c + 3, (c + 3) & 3); else CP_COMMIT();

        uint32_t s0 = sb + (c & 3) * STAGE;
        #pragma unroll
        for (int ks = 0; ks < 4; ks++) {
            uint32_t a[MF][4], b[NBB][4];
            uint32_t arow = warp_m * WTM + (lane & 15);
            uint32_t acol = (ks * 16 + (lane >> 4) * 8) * 2;
            #pragma unroll
            for (int mf = 0; mf < MF; mf++)
                LDMATRIX_X4(a[mf], s0 + (arow + mf * 16) * ROWB + acol);
            uint32_t brow = warp_n * WTN + (lane & 7) + ((lane >> 4) & 1) * 8;
            uint32_t bcol = (ks * 16 + ((lane >> 3) & 1) * 8) * 2;
            #pragma unroll
            for (int nb = 0; nb < NBB; nb++)
                LDMATRIX_X4(b[nb], s0 + SMA + (brow + nb * 16) * ROWB + bcol);
            #pragma unroll
            for (int mf = 0; mf < MF; mf++)
                #pragma unroll
                for (int nf = 0; nf < NF; nf++)
                    MMA16816(acc[mf][nf], a[mf], b[nf >> 1][(nf & 1) * 2], b[nf >> 1][(nf & 1) * 2 + 1]);
        }
    }

    if (MAXEPI) {
        __half* fout = (__half*)outp;
        #pragma unroll
        for (int mf = 0; mf < MF; mf++) {
            int nrow = bm * (BM / 16) + warp_m * MF + mf;    // batch index
            #pragma unroll
            for (int nf = 0; nf < NF; nf++) {
                float m0 = fmaxf(acc[mf][nf][0], acc[mf][nf][2]);
                float m1 = fmaxf(acc[mf][nf][1], acc[mf][nf][3]);
                #pragma unroll
                for (int o = 4; o < 32; o <<= 1) {
                    m0 = fmaxf(m0, __shfl_xor_sync(0xffffffffu, m0, o));
                    m1 = fmaxf(m1, __shfl_xor_sync(0xffffffffu, m1, o));
                }
                if (lane < 4) {
                    int col = OO + bn * BN + warp_n * WTN + nf * 8 + lane * 2;
                    __half2 h = __floats2half2_rn(m0, m1);
                    *(__half2*)&fout[(size_t)nrow * (2 * OO) + col] = h;
                }
            }
        }
    } else {
        float* out = (float*)outp + (size_t)blockIdx.z * NB * OO;
        #pragma unroll
        for (int mf = 0; mf < MF; mf++) {
            int r0 = bm * BM + warp_m * WTM + mf * 16 + (lane >> 2);
            #pragma unroll
            for (int nf = 0; nf < NF; nf++) {
                int col = bn * BN + warp_n * WTN + nf * 8 + (lane & 3) * 2;
                *(float2*)&out[(size_t)r0 * OO + col] =
                    make_float2(acc[mf][nf][0], acc[mf][nf][1]);
                *(float2*)&out[(size_t)(r0 + 8) * OO + col] =
                    make_float2(acc[mf][nf][2], acc[mf][nf][3]);
            }
        }
    }
}

// ---------------------------------------------------------------------------
// Kernel 4: sum split-K partials + row L2 normalize -> out
// 2 rows per block (grid NB/2), float4 loads. Warps 0-3 row 0, warps 4-7 row 1.
// ---------------------------------------------------------------------------
__global__ void normalize_kernel(float* __restrict__ out) {
    __shared__ float red[8];
    __shared__ float invs[2];

    int t = threadIdx.x;
    int r = t >> 7;                      // 0 or 1 (local row)
    int c = t & 127;                     // float4 index within row
    int n = blockIdx.x * 2 + r;
    int warp = t >> 5, lane = t & 31;

    float4 a = ((const float4*)(g_P + (size_t)n * OO))[c];
    float4 b = ((const float4*)(g_P + (size_t)(NB + n) * OO))[c];
    float4 v = make_float4(a.x + b.x, a.y + b.y, a.z + b.z, a.w + b.w);
    float s = v.x * v.x + v.y * v.y + v.z * v.z + v.w * v.w;
    #pragma unroll
    for (int o = 16; o; o >>= 1) s += __shfl_xor_sync(0xffffffffu, s, o);
    if (lane == 0) red[warp] = s;
    __syncthreads();
    if (t < 2) {
        float tot = red[t * 4] + red[t * 4 + 1] + red[t * 4 + 2] + red[t * 4 + 3];
        invs[t] = 1.f / fmaxf(sqrtf(tot), 1e-12f);
    }
    __syncthreads();
    float inv = invs[r];
    v.x *= inv; v.y *= inv; v.z *= inv; v.w *= inv;
    ((float4*)(out + (size_t)n * OO))[c] = v;
}

// ---------------------------------------------------------------------------
extern "C" void kernel_launch(void* const* d_in, const int* in_sizes, int n_in,
                              void* d_out, int out_size) {
    const float* cls = (const float*)d_in[0];   // (2048, 512)
    const float* pt  = (const float*)d_in[1];   // (2048, 196, 768)
    const float* Wp  = (const float*)d_in[2];   // (512, 768)
    const float* Wf  = (const float*)d_in[3];   // (512, 1024)
    float* out = (float*)d_out;                 // (2048, 512)

    __half *a_p, *f_p, *wp_p, *wf_p;
    float* p_p;
    cudaGetSymbolAddress((void**)&a_p,  g_A);
    cudaGetSymbolAddress((void**)&f_p,  g_F);
    cudaGetSymbolAddress((void**)&wp_p, g_WpH);
    cudaGetSymbolAddress((void**)&wf_p, g_WfH);
    cudaGetSymbolAddress((void**)&p_p,  g_P);

    // local GEMM: BM=128, BN=256 -> grid (2, 256) = 512 CTAs
    constexpr int SM_LOCAL = 4 * (128 + 256) * ROWB;   // 221184
    // fuse GEMM: BM=64, BN=128, split-K=2 -> grid (4, 32, 2) = 256 CTAs
    constexpr int SM_FUSE  = 4 * (64 + 128) * ROWB;    // 110592

    cudaFuncSetAttribute(gemm_mma<128, 256, DD / 64, true>,
                         cudaFuncAttributeMaxDynamicSharedMemorySize, SM_LOCAL);
    cudaFuncSetAttribute(gemm_mma<64, 128, (2 * OO) / 128, false>,
                         cudaFuncAttributeMaxDynamicSharedMemorySize, SM_FUSE);

    norm_topk_kernel<<<NB + PREP_BLOCKS, 512>>>(pt, Wp, Wf, cls);
    gemm_mma<128, 256, DD / 64, true><<<dim3(OO / 256, MTOT / 128), 256, SM_LOCAL>>>(
        a_p, wp_p, DD, f_p);
    gemm_mma<64, 128, (2 * OO) / 128, false>
        <<<dim3(OO / 128, NB / 64, 2), 256, SM_FUSE>>>(f_p, wf_p, 2 * OO, p_p);
    normalize_kernel<<<NB / 2, 256>>>(out);
}